// round 7
// baseline (speedup 1.0000x reference)
#include <cuda_runtime.h>

// out[m,k] = D*(w-1)*sum_j t[m,j], broadcast over k. M=16384, D=2048.
// Persistent grid-stride kernel: 1184 CTAs (148 SMs x occ 8), each processes
// ~14 rows. Next row's loads are prefetched before the current row's barrier
// and store, keeping memory in flight across row boundaries and eliminating
// wave-transition / CTA cold-start overhead.

#define M_ROWS 16384
#define D_COLS 2048
#define NTHREADS 256
#define NWARPS (NTHREADS / 32)
#define GRID_CTAS (148 * 8)

__global__ __launch_bounds__(NTHREADS)
void perm_equiv_kernel(const float* __restrict__ t,
                       const float* __restrict__ w,
                       float* __restrict__ out) {
    const int tid  = threadIdx.x;
    const int lane = tid & 31;
    const int wid  = tid >> 5;

    __shared__ float warp_sums[NWARPS];

    const float scale = (float)D_COLS * (__ldg(w) - 1.0f);

    int m = blockIdx.x;

    // Prime: load first row
    const float4* row = reinterpret_cast<const float4*>(t + (size_t)m * D_COLS);
    float4 a = __ldcs(row + tid);
    float4 b = __ldcs(row + tid + NTHREADS);

    while (true) {
        const int m_next = m + GRID_CTAS;
        float4 an, bn;
        const bool has_next = (m_next < M_ROWS);
        if (has_next) {
            // Prefetch next row BEFORE the barrier/store of this row
            const float4* nrow =
                reinterpret_cast<const float4*>(t + (size_t)m_next * D_COLS);
            an = __ldcs(nrow + tid);
            bn = __ldcs(nrow + tid + NTHREADS);
        }

        // Reduce current row
        float s = ((a.x + a.y) + (a.z + a.w)) + ((b.x + b.y) + (b.z + b.w));
        #pragma unroll
        for (int off = 16; off > 0; off >>= 1)
            s += __shfl_xor_sync(0xFFFFFFFFu, s, off);

        if (lane == 0) warp_sums[wid] = s;
        __syncthreads();

        float total = 0.f;
        #pragma unroll
        for (int i = 0; i < NWARPS; i++) total += warp_sums[i];
        __syncthreads();   // protect warp_sums reuse next iteration

        const float v = scale * total;
        const float4 vv = make_float4(v, v, v, v);
        float4* orow = reinterpret_cast<float4*>(out + (size_t)m * D_COLS);
        __stcs(orow + tid, vv);
        __stcs(orow + tid + NTHREADS, vv);

        if (!has_next) break;
        m = m_next;
        a = an;
        b = bn;
    }
}

extern "C" void kernel_launch(void* const* d_in, const int* in_sizes, int n_in,
                              void* d_out, int out_size) {
    const float* t = (const float*)d_in[0];
    const float* w = (const float*)d_in[1];
    float* out = (float*)d_out;
    perm_equiv_kernel<<<GRID_CTAS, NTHREADS>>>(t, w, out);
}